// round 5
// baseline (speedup 1.0000x reference)
#include <cuda_runtime.h>
#include <cuda_bf16.h>
#include <cstdint>

// out[g] = x[g] @ Q[g], Q = H_0..H_127 (Householder composition).
// Kernel A: build Q rows in parallel, emit Q^T (k-major) as bf16 hi/lo.
// Kernel B: mma.sync bf16 GEMM, 3-product hi/lo split; each warp owns TWO
//           m16 tiles so every B fragment load feeds 12 MMAs (B-traffic /2).

#define G 16
#define MROWS 16384
#define C 128
#define MT 256         // m-tile per CTA
#define SP 136         // padded smem row stride in bf16 elements

__device__ __nv_bfloat16 Qt_hi[G * C * C];  // [g][n][k], k contiguous
__device__ __nv_bfloat16 Qt_lo[G * C * C];

__device__ __forceinline__ uint32_t smem_u32(const void* p) {
    uint32_t a;
    asm("{ .reg .u64 t; cvta.to.shared.u64 t, %1; cvt.u32.u64 %0, t; }"
        : "=r"(a) : "l"(p));
    return a;
}

__device__ __forceinline__ void ldmatrix_x4(uint32_t& r0, uint32_t& r1,
                                            uint32_t& r2, uint32_t& r3,
                                            uint32_t addr) {
    asm volatile("ldmatrix.sync.aligned.m8n8.x4.shared.b16 {%0,%1,%2,%3}, [%4];"
                 : "=r"(r0), "=r"(r1), "=r"(r2), "=r"(r3) : "r"(addr));
}

__device__ __forceinline__ void mma_bf16(float* d, const uint32_t* a,
                                         uint32_t b0, uint32_t b1) {
    asm volatile(
        "mma.sync.aligned.m16n8k16.row.col.f32.bf16.bf16.f32 "
        "{%0,%1,%2,%3}, {%4,%5,%6,%7}, {%8,%9}, {%0,%1,%2,%3};"
        : "+f"(d[0]), "+f"(d[1]), "+f"(d[2]), "+f"(d[3])
        : "r"(a[0]), "r"(a[1]), "r"(a[2]), "r"(a[3]), "r"(b0), "r"(b1));
}

// ==================== Kernel A: build Q (transposed, bf16 hi/lo) ====================
__global__ void __launch_bounds__(128) buildq_kernel(const float* __restrict__ W) {
    extern __shared__ float sm[];
    float* WshT = sm;              // [128][129]
    float* rden = sm + 128 * 129;  // [128]

    const int g  = blockIdx.x >> 3;
    const int rb = blockIdx.x & 7;
    const float* Wg = W + (size_t)g * C * C;
    const int t = threadIdx.x;

    #pragma unroll 8
    for (int k = 0; k < C; k++) WshT[t * 129 + k] = Wg[k * C + t];
    __syncthreads();

    {
        const float* row = &WshT[t * 129];
        float s = 0.0f;
        #pragma unroll 8
        for (int k = 0; k < C; k++) s = fmaf(row[k], row[k], s);
        rden[t] = 2.0f / s;
    }
    __syncthreads();

    const int r = t >> 3;
    const int p = t & 7;
    const int R = rb * 16 + r;  // row of Q (= K index of Q^T)

    float M[16];
    #pragma unroll
    for (int j = 0; j < 16; j++) M[j] = (R == (p + 8 * j)) ? 1.0f : 0.0f;

    for (int i = 0; i < C; i++) {
        const float* wrow = &WshT[i * 129 + p];
        float wv[16];
        float d0 = 0.0f, d1 = 0.0f;
        #pragma unroll
        for (int j = 0; j < 16; j++) {
            wv[j] = wrow[8 * j];
            if (j & 1) d1 = fmaf(M[j], wv[j], d1);
            else       d0 = fmaf(M[j], wv[j], d0);
        }
        float d = d0 + d1;
        d += __shfl_xor_sync(0xffffffffu, d, 1, 8);
        d += __shfl_xor_sync(0xffffffffu, d, 2, 8);
        d += __shfl_xor_sync(0xffffffffu, d, 4, 8);
        const float c = d * rden[i];
        #pragma unroll
        for (int j = 0; j < 16; j++) M[j] = fmaf(-c, wv[j], M[j]);
    }

    #pragma unroll
    for (int j = 0; j < 16; j++) {
        const int n = p + 8 * j;
        const size_t idx = ((size_t)g * C + n) * C + R;
        __nv_bfloat16 hi = __float2bfloat16_rn(M[j]);
        __nv_bfloat16 lo = __float2bfloat16_rn(M[j] - __bfloat162float(hi));
        Qt_hi[idx] = hi;
        Qt_lo[idx] = lo;
    }
}

// ==================== Kernel B: mma.sync GEMM, 2 m-tiles per warp ====================
#define AH_OFF 0
#define AL_OFF (MT * SP * 2)
#define BH_OFF (2 * MT * SP * 2)
#define BL_OFF (2 * MT * SP * 2 + C * SP * 2)
#define SMEM_MMA (2 * MT * SP * 2 + 2 * C * SP * 2)   // 208896 bytes

__global__ void __launch_bounds__(256, 1) mma_kernel(const float* __restrict__ X,
                                                     float* __restrict__ Out) {
    extern __shared__ char smem[];
    const uint32_t sb = smem_u32(smem);
    const int t  = threadIdx.x;
    const int w  = t >> 5;   // warp 0..7: owns m rows [16w,16w+16) and [16w+128,+16)
    const int l  = t & 31;
    const int m0 = blockIdx.x * MT;
    const int g  = blockIdx.y;

    // ---- stage Q^T hi/lo (128 x 128 bf16 each) ----
    const uint4* qh = (const uint4*)(Qt_hi + (size_t)g * C * C);
    const uint4* ql = (const uint4*)(Qt_lo + (size_t)g * C * C);
    #pragma unroll
    for (int it = 0; it < 8; it++) {
        const int idx = t + 256 * it;          // 2048 uint4 per tile
        const int row = idx >> 4;
        const int c8  = (idx & 15) * 8;
        const uint32_t off = (uint32_t)(row * SP + c8) * 2;
        *(uint4*)(smem + BH_OFF + off) = qh[idx];
        *(uint4*)(smem + BL_OFF + off) = ql[idx];
    }

    // ---- stage x tile (256 x 128 fp32) -> bf16 hi/lo ----
    const float4* xg = (const float4*)(X + ((size_t)g * MROWS + m0) * C);
    #pragma unroll
    for (int it = 0; it < 32; it++) {
        const int idx = t + 256 * it;          // 8192 float4
        const int row = idx >> 5;
        const int c4  = (idx & 31) * 4;
        const float4 v = xg[idx];
        const float vv[4] = {v.x, v.y, v.z, v.w};
        __nv_bfloat16 h[4], e[4];
        #pragma unroll
        for (int i = 0; i < 4; i++) {
            h[i] = __float2bfloat16_rn(vv[i]);
            e[i] = __float2bfloat16_rn(vv[i] - __bfloat162float(h[i]));
        }
        const uint32_t off = (uint32_t)(row * SP + c4) * 2;
        *(uint2*)(smem + AH_OFF + off) = *(const uint2*)h;
        *(uint2*)(smem + AL_OFF + off) = *(const uint2*)e;
    }

    __syncthreads();

    // ---- mainloop ----
    float acc[2][16][4];
    #pragma unroll
    for (int mt = 0; mt < 2; mt++)
        #pragma unroll
        for (int nt = 0; nt < 16; nt++)
            #pragma unroll
            for (int i = 0; i < 4; i++) acc[mt][nt][i] = 0.0f;

    const int a_row  = (l & 7) + 8 * ((l >> 3) & 1);
    const int a_col8 = 8 * (l >> 4);
    const int b_row_in = (l & 7) + 8 * (l >> 4);
    const int b_col8   = 8 * ((l >> 3) & 1);

    const uint32_t aoff0 = (uint32_t)((16 * w + a_row) * SP + a_col8) * 2;
    const uint32_t aoff1 = (uint32_t)((16 * w + 128 + a_row) * SP + a_col8) * 2;

    #pragma unroll
    for (int ks = 0; ks < 8; ks++) {
        const int k0 = 16 * ks;
        uint32_t ah0[4], al0[4], ah1[4], al1[4];
        ldmatrix_x4(ah0[0], ah0[1], ah0[2], ah0[3], sb + AH_OFF + aoff0 + k0 * 2);
        ldmatrix_x4(al0[0], al0[1], al0[2], al0[3], sb + AL_OFF + aoff0 + k0 * 2);
        ldmatrix_x4(ah1[0], ah1[1], ah1[2], ah1[3], sb + AH_OFF + aoff1 + k0 * 2);
        ldmatrix_x4(al1[0], al1[1], al1[2], al1[3], sb + AL_OFF + aoff1 + k0 * 2);

        #pragma unroll
        for (int j = 0; j < 8; j++) {
            const uint32_t boff =
                (uint32_t)((16 * j + b_row_in) * SP + k0 + b_col8) * 2;
            uint32_t bh0, bh1, bh2, bh3, bl0, bl1, bl2, bl3;
            ldmatrix_x4(bh0, bh1, bh2, bh3, sb + BH_OFF + boff);
            ldmatrix_x4(bl0, bl1, bl2, bl3, sb + BL_OFF + boff);

            // m-tile 0
            mma_bf16(acc[0][2 * j],     ah0, bh0, bh1);
            mma_bf16(acc[0][2 * j],     ah0, bl0, bl1);
            mma_bf16(acc[0][2 * j],     al0, bh0, bh1);
            mma_bf16(acc[0][2 * j + 1], ah0, bh2, bh3);
            mma_bf16(acc[0][2 * j + 1], ah0, bl2, bl3);
            mma_bf16(acc[0][2 * j + 1], al0, bh2, bh3);
            // m-tile 1
            mma_bf16(acc[1][2 * j],     ah1, bh0, bh1);
            mma_bf16(acc[1][2 * j],     ah1, bl0, bl1);
            mma_bf16(acc[1][2 * j],     al1, bh0, bh1);
            mma_bf16(acc[1][2 * j + 1], ah1, bh2, bh3);
            mma_bf16(acc[1][2 * j + 1], ah1, bl2, bl3);
            mma_bf16(acc[1][2 * j + 1], al1, bh2, bh3);
        }
    }

    // ---- epilogue ----
    const int rr = l >> 2;
    const int cn = 2 * (l & 3);
    #pragma unroll
    for (int mt = 0; mt < 2; mt++) {
        const int r0 = 16 * w + 128 * mt + rr;
        float* ob = Out + ((size_t)g * MROWS + m0 + r0) * C + cn;
        #pragma unroll
        for (int nt = 0; nt < 16; nt++) {
            *(float2*)(ob + 8 * nt)         = make_float2(acc[mt][nt][0], acc[mt][nt][1]);
            *(float2*)(ob + 8 * C + 8 * nt) = make_float2(acc[mt][nt][2], acc[mt][nt][3]);
        }
    }
}

// ==================== launch ====================
extern "C" void kernel_launch(void* const* d_in, const int* in_sizes, int n_in,
                              void* d_out, int out_size) {
    const float* x = (const float*)d_in[0];
    const float* w = (const float*)d_in[1];
    if (n_in >= 2 && in_sizes[0] < in_sizes[1]) {
        const float* tmp = x; x = w; w = tmp;
    }
    float* out = (float*)d_out;

    const int smemA = 128 * 129 * 4 + 128 * 4;  // 66560
    cudaFuncSetAttribute((const void*)buildq_kernel,
                         cudaFuncAttributeMaxDynamicSharedMemorySize, smemA);
    cudaFuncSetAttribute((const void*)mma_kernel,
                         cudaFuncAttributeMaxDynamicSharedMemorySize, SMEM_MMA);

    buildq_kernel<<<G * 8, 128, smemA>>>(w);
    mma_kernel<<<dim3(MROWS / MT, G), 256, SMEM_MMA>>>(x, out);
}

// round 6
// speedup vs baseline: 1.1326x; 1.1326x over previous
#include <cuda_runtime.h>
#include <cuda_bf16.h>
#include <cstdint>

// out[g] = x[g] @ Q[g], Q = H_0..H_127 (Householder composition).
// Kernel A: build Q rows in parallel, emit Q^T (k-major) as bf16 hi/lo.
// Kernel B: mma.sync bf16 GEMM, 3-product hi/lo split. MT=64, 256 thr
//           (4m x 2n warps), 2 CTAs/SM for stage/MMA overlap + MLP.

#define G 16
#define MROWS 16384
#define C 128
#define MT 64          // m-tile per CTA
#define SP 136         // padded smem row stride in bf16 elements

__device__ __nv_bfloat16 Qt_hi[G * C * C];  // [g][n][k], k contiguous
__device__ __nv_bfloat16 Qt_lo[G * C * C];

__device__ __forceinline__ uint32_t smem_u32(const void* p) {
    uint32_t a;
    asm("{ .reg .u64 t; cvta.to.shared.u64 t, %1; cvt.u32.u64 %0, t; }"
        : "=r"(a) : "l"(p));
    return a;
}

__device__ __forceinline__ void cp_async16(uint32_t saddr, const void* gaddr) {
    asm volatile("cp.async.cg.shared.global [%0], [%1], 16;"
                 :: "r"(saddr), "l"(gaddr) : "memory");
}
__device__ __forceinline__ void cp_async_commit_wait() {
    asm volatile("cp.async.commit_group;" ::: "memory");
    asm volatile("cp.async.wait_group 0;" ::: "memory");
}

__device__ __forceinline__ void ldmatrix_x4(uint32_t& r0, uint32_t& r1,
                                            uint32_t& r2, uint32_t& r3,
                                            uint32_t addr) {
    asm volatile("ldmatrix.sync.aligned.m8n8.x4.shared.b16 {%0,%1,%2,%3}, [%4];"
                 : "=r"(r0), "=r"(r1), "=r"(r2), "=r"(r3) : "r"(addr));
}

__device__ __forceinline__ void mma_bf16(float* d, const uint32_t* a,
                                         uint32_t b0, uint32_t b1) {
    asm volatile(
        "mma.sync.aligned.m16n8k16.row.col.f32.bf16.bf16.f32 "
        "{%0,%1,%2,%3}, {%4,%5,%6,%7}, {%8,%9}, {%0,%1,%2,%3};"
        : "+f"(d[0]), "+f"(d[1]), "+f"(d[2]), "+f"(d[3])
        : "r"(a[0]), "r"(a[1]), "r"(a[2]), "r"(a[3]), "r"(b0), "r"(b1));
}

// ==================== Kernel A: build Q (transposed, bf16 hi/lo) ====================
__global__ void __launch_bounds__(128) buildq_kernel(const float* __restrict__ W) {
    extern __shared__ float sm[];
    float* WshT = sm;              // [128][129]
    float* rden = sm + 128 * 129;  // [128]

    const int g  = blockIdx.x >> 3;
    const int rb = blockIdx.x & 7;
    const float* Wg = W + (size_t)g * C * C;
    const int t = threadIdx.x;

    #pragma unroll 8
    for (int k = 0; k < C; k++) WshT[t * 129 + k] = Wg[k * C + t];
    __syncthreads();

    {
        const float* row = &WshT[t * 129];
        float s = 0.0f;
        #pragma unroll 8
        for (int k = 0; k < C; k++) s = fmaf(row[k], row[k], s);
        rden[t] = 2.0f / s;
    }
    __syncthreads();

    const int r = t >> 3;
    const int p = t & 7;
    const int R = rb * 16 + r;  // row of Q (= K index of Q^T)

    float M[16];
    #pragma unroll
    for (int j = 0; j < 16; j++) M[j] = (R == (p + 8 * j)) ? 1.0f : 0.0f;

    for (int i = 0; i < C; i++) {
        const float* wrow = &WshT[i * 129 + p];
        float wv[16];
        float d0 = 0.0f, d1 = 0.0f;
        #pragma unroll
        for (int j = 0; j < 16; j++) {
            wv[j] = wrow[8 * j];
            if (j & 1) d1 = fmaf(M[j], wv[j], d1);
            else       d0 = fmaf(M[j], wv[j], d0);
        }
        float d = d0 + d1;
        d += __shfl_xor_sync(0xffffffffu, d, 1, 8);
        d += __shfl_xor_sync(0xffffffffu, d, 2, 8);
        d += __shfl_xor_sync(0xffffffffu, d, 4, 8);
        const float c = d * rden[i];
        #pragma unroll
        for (int j = 0; j < 16; j++) M[j] = fmaf(-c, wv[j], M[j]);
    }

    #pragma unroll
    for (int j = 0; j < 16; j++) {
        const int n = p + 8 * j;
        const size_t idx = ((size_t)g * C + n) * C + R;
        __nv_bfloat16 hi = __float2bfloat16_rn(M[j]);
        __nv_bfloat16 lo = __float2bfloat16_rn(M[j] - __bfloat162float(hi));
        Qt_hi[idx] = hi;
        Qt_lo[idx] = lo;
    }
}

// ==================== Kernel B: mma.sync GEMM, 4m x 2n warps ====================
#define AH_OFF 0
#define AL_OFF (MT * SP * 2)
#define BH_OFF (2 * MT * SP * 2)
#define BL_OFF (2 * MT * SP * 2 + C * SP * 2)
#define SMEM_MMA (2 * MT * SP * 2 + 2 * C * SP * 2)   // 104448 bytes

__global__ void __launch_bounds__(256, 2) mma_kernel(const float* __restrict__ X,
                                                     float* __restrict__ Out) {
    extern __shared__ char smem[];
    const uint32_t sb = smem_u32(smem);
    const int t  = threadIdx.x;
    const int w  = t >> 5;
    const int l  = t & 31;
    const int wm = w & 3;    // m-warp: rows [16*wm, 16*wm+16)
    const int wn = w >> 2;   // n-warp: cols [64*wn, 64*wn+64)
    const int m0 = blockIdx.x * MT;
    const int g  = blockIdx.y;

    // ---- stage Q^T hi/lo via cp.async (raw bf16 copy) ----
    const char* qh = (const char*)(Qt_hi + (size_t)g * C * C);
    const char* ql = (const char*)(Qt_lo + (size_t)g * C * C);
    #pragma unroll
    for (int it = 0; it < 8; it++) {
        const int idx = t + 256 * it;          // uint4 chunks (8 bf16)
        const int row = idx >> 4;
        const int c8  = (idx & 15) * 8;
        const uint32_t off = (uint32_t)(row * SP + c8) * 2;
        cp_async16(sb + BH_OFF + off, qh + idx * 16);
        cp_async16(sb + BL_OFF + off, ql + idx * 16);
    }

    // ---- stage x tile (64 x 128 fp32) -> bf16 hi/lo ----
    const float4* xg = (const float4*)(X + ((size_t)g * MROWS + m0) * C);
    #pragma unroll
    for (int it = 0; it < 8; it++) {
        const int idx = t + 256 * it;          // 2048 float4
        const int row = idx >> 5;
        const int c4  = (idx & 31) * 4;
        const float4 v = xg[idx];
        const float vv[4] = {v.x, v.y, v.z, v.w};
        __nv_bfloat16 h[4], e[4];
        #pragma unroll
        for (int i = 0; i < 4; i++) {
            h[i] = __float2bfloat16_rn(vv[i]);
            e[i] = __float2bfloat16_rn(vv[i] - __bfloat162float(h[i]));
        }
        const uint32_t off = (uint32_t)(row * SP + c4) * 2;
        *(uint2*)(smem + AH_OFF + off) = *(const uint2*)h;
        *(uint2*)(smem + AL_OFF + off) = *(const uint2*)e;
    }

    cp_async_commit_wait();
    __syncthreads();

    // ---- mainloop ----
    float acc[8][4];
    #pragma unroll
    for (int nt = 0; nt < 8; nt++)
        #pragma unroll
        for (int i = 0; i < 4; i++) acc[nt][i] = 0.0f;

    const int a_row  = (l & 7) + 8 * ((l >> 3) & 1);
    const int a_col8 = 8 * (l >> 4);
    const int b_row_in = (l & 7) + 8 * (l >> 4);
    const int b_col8   = 8 * ((l >> 3) & 1);

    const uint32_t aoff = (uint32_t)((16 * wm + a_row) * SP + a_col8) * 2;

    #pragma unroll
    for (int ks = 0; ks < 8; ks++) {
        const int k0 = 16 * ks;
        uint32_t ah[4], al[4];
        ldmatrix_x4(ah[0], ah[1], ah[2], ah[3], sb + AH_OFF + aoff + k0 * 2);
        ldmatrix_x4(al[0], al[1], al[2], al[3], sb + AL_OFF + aoff + k0 * 2);

        #pragma unroll
        for (int jj = 0; jj < 4; jj++) {
            const uint32_t boff =
                (uint32_t)((64 * wn + 16 * jj + b_row_in) * SP + k0 + b_col8) * 2;
            uint32_t bh0, bh1, bh2, bh3, bl0, bl1, bl2, bl3;
            ldmatrix_x4(bh0, bh1, bh2, bh3, sb + BH_OFF + boff);
            ldmatrix_x4(bl0, bl1, bl2, bl3, sb + BL_OFF + boff);

            mma_bf16(acc[2 * jj],     ah, bh0, bh1);
            mma_bf16(acc[2 * jj],     ah, bl0, bl1);
            mma_bf16(acc[2 * jj],     al, bh0, bh1);
            mma_bf16(acc[2 * jj + 1], ah, bh2, bh3);
            mma_bf16(acc[2 * jj + 1], ah, bl2, bl3);
            mma_bf16(acc[2 * jj + 1], al, bh2, bh3);
        }
    }

    // ---- epilogue ----
    const int r0 = 16 * wm + (l >> 2);
    const int cn = 64 * wn + 2 * (l & 3);
    float* ob = Out + ((size_t)g * MROWS + m0 + r0) * C + cn;
    #pragma unroll
    for (int nt = 0; nt < 8; nt++) {
        *(float2*)(ob + 8 * nt)         = make_float2(acc[nt][0], acc[nt][1]);
        *(float2*)(ob + 8 * C + 8 * nt) = make_float2(acc[nt][2], acc[nt][3]);
    }
}

// ==================== launch ====================
extern "C" void kernel_launch(void* const* d_in, const int* in_sizes, int n_in,
                              void* d_out, int out_size) {
    const float* x = (const float*)d_in[0];
    const float* w = (const float*)d_in[1];
    if (n_in >= 2 && in_sizes[0] < in_sizes[1]) {
        const float* tmp = x; x = w; w = tmp;
    }
    float* out = (float*)d_out;

    const int smemA = 128 * 129 * 4 + 128 * 4;  // 66560
    cudaFuncSetAttribute((const void*)buildq_kernel,
                         cudaFuncAttributeMaxDynamicSharedMemorySize, smemA);
    cudaFuncSetAttribute((const void*)mma_kernel,
                         cudaFuncAttributeMaxDynamicSharedMemorySize, SMEM_MMA);

    buildq_kernel<<<G * 8, 128, smemA>>>(w);
    mma_kernel<<<dim3(MROWS / MT, G), 256, SMEM_MMA>>>(x, out);
}